// round 14
// baseline (speedup 1.0000x reference)
#include <cuda_runtime.h>
#include <cuda_fp16.h>
#include <cstdint>

// FeatureDictionary — fp16-codebook pipeline:
//  P1: face table int4 expand (smpl_F -> g_faceVerts)
//  P2: convert active subjects' codebooks f32 -> fp16 (row = 128B = 1 line)
//  K : fused 16:1 block-specialized kernel
//      gather blocks: 16 lanes/point, 3 one-line gathers, 1 coalesced store
//      tail blocks:   normal + coords_feats streaming
//  0 coords [B,S,3] f32   1 idx [B] i32         2 smpl_F [13776,3] i32
//  3 fid [B,S] i32        4 weights [B,S,3] f32  5 sdf [B,S,1] f32
//  6 hitpt [B,S,3] f32    7 codebooks [256,6890,64] f32
// Output: concat( weighted_feats [B,S,64], coords_feats [B,S,3], normal [B,S,3] )

#define NUM_VERTICES 6890
#define NUM_FACES_MAX 16384
#define DFEAT 64
#define MAXB 8

__device__ int4   g_faceVerts[NUM_FACES_MAX];
__device__ __half g_cbh[MAXB * NUM_VERTICES * DFEAT];   // 7MB scratch

__global__ __launch_bounds__(256)
void face_table_kernel(const int* __restrict__ smpl_F, int nFaces)
{
    int t = blockIdx.x * blockDim.x + threadIdx.x;
    if (t >= nFaces) return;
    int v0 = __ldg(smpl_F + 3 * t + 0);
    int v1 = __ldg(smpl_F + 3 * t + 1);
    int v2 = __ldg(smpl_F + 3 * t + 2);
    g_faceVerts[t] = make_int4(v0, v1, v2, 0);
}

// Convert subject idx[b]'s codebook to fp16 into g_cbh[b].
__global__ __launch_bounds__(256)
void convert_kernel(const int* __restrict__ idx,
                    const float* __restrict__ codebooks)
{
    int b = blockIdx.y;
    int subj = __ldg(idx + b);
    const float4* src = (const float4*)(codebooks
                        + (size_t)subj * (NUM_VERTICES * DFEAT));
    uint2* dst = (uint2*)(g_cbh + (size_t)b * (NUM_VERTICES * DFEAT));

    int t = blockIdx.x * blockDim.x + threadIdx.x;   // one float4 -> one uint2
    int total = NUM_VERTICES * DFEAT / 4;
    if (t >= total) return;
    float4 v = __ldcs(src + t);
    __half2 lo = __floats2half2_rn(v.x, v.y);
    __half2 hi = __floats2half2_rn(v.z, v.w);
    uint2 o;
    o.x = *(unsigned*)&lo;
    o.y = *(unsigned*)&hi;
    dst[t] = o;
}

__global__ __launch_bounds__(256)
void fused_kernel(const float* __restrict__ coords,
                  const int*   __restrict__ fid,
                  const float* __restrict__ weights,
                  const float* __restrict__ sdf,
                  const float* __restrict__ hitpt,
                  float*       __restrict__ out,
                  int BS, int S, int Sshift)
{
    // Block-type decode: every 17th block (r==16) is a tail block.
    int blk = blockIdx.x;
    int q   = blk / 17;
    int r   = blk - q * 17;

    if (r == 16) {
        int p = q * 256 + threadIdx.x;
        if (p >= BS) return;

        size_t C_OFF = (size_t)BS * DFEAT;
        size_t N_OFF = C_OFF + (size_t)BS * 3;

        float cx = __ldcs(coords + 3 * p + 0);
        float cy = __ldcs(coords + 3 * p + 1);
        float cz = __ldcs(coords + 3 * p + 2);
        float hx = __ldcs(hitpt  + 3 * p + 0);
        float hy = __ldcs(hitpt  + 3 * p + 1);
        float hz = __ldcs(hitpt  + 3 * p + 2);
        float w1 = __ldcs(weights + 3 * p + 1);
        float w2 = __ldcs(weights + 3 * p + 2);
        float sd = __ldcs(sdf + p);

        float dx = hx - cx, dy = hy - cy, dz = hz - cz;
        float nrm = sqrtf(dx * dx + dy * dy + dz * dz);
        float inv = 1.0f / fmaxf(nrm, 1e-6f);

        __stcs(out + N_OFF + 3 * (size_t)p + 0, dx * inv);
        __stcs(out + N_OFF + 3 * (size_t)p + 1, dy * inv);
        __stcs(out + N_OFF + 3 * (size_t)p + 2, dz * inv);
        __stcs(out + C_OFF + 3 * (size_t)p + 0, w1);
        __stcs(out + C_OFF + 3 * (size_t)p + 1, w2);
        __stcs(out + C_OFF + 3 * (size_t)p + 2, sd);
        return;
    }

    // ---- gather path: 16 lanes per point, fp16 rows (128B = 1 line) ----
    int gblk = q * 16 + r;
    int L    = gblk * 256 + threadIdx.x;
    int p    = L >> 4;
    int lane = L & 15;
    if (p >= BS) return;

    int b = (Sshift >= 0) ? (p >> Sshift) : (p / S);
    const __half* cb = g_cbh + (size_t)b * (NUM_VERTICES * DFEAT);

    int f = __ldcs(fid + p);
    int4 v = __ldg(&g_faceVerts[f]);

    float w0 = __ldcs(weights + 3 * p + 0);
    float w1 = __ldcs(weights + 3 * p + 1);
    float w2 = __ldcs(weights + 3 * p + 2);

    // One 8B load per row per lane: 16 lanes cover the full 128B row/line.
    const uint2* r0 = (const uint2*)(cb + (size_t)v.x * DFEAT);
    const uint2* r1 = (const uint2*)(cb + (size_t)v.y * DFEAT);
    const uint2* r2 = (const uint2*)(cb + (size_t)v.z * DFEAT);

    uint2 A = __ldg(r0 + lane);
    uint2 C = __ldg(r1 + lane);
    uint2 D = __ldg(r2 + lane);

    float2 a01 = __half22float2(*(__half2*)&A.x);
    float2 a23 = __half22float2(*(__half2*)&A.y);
    float2 c01 = __half22float2(*(__half2*)&C.x);
    float2 c23 = __half22float2(*(__half2*)&C.y);
    float2 d01 = __half22float2(*(__half2*)&D.x);
    float2 d23 = __half22float2(*(__half2*)&D.y);

    float4 o;
    o.x = w0 * a01.x + w1 * c01.x + w2 * d01.x;
    o.y = w0 * a01.y + w1 * c01.y + w2 * d01.y;
    o.z = w0 * a23.x + w1 * c23.x + w2 * d23.x;
    o.w = w0 * a23.y + w1 * c23.y + w2 * d23.y;
    (void)d23; // all used above

    // lane's 4 halves map to output floats [4*lane, 4*lane+4): one coalesced
    // float4 store; 16 lanes cover the point's full 256B output.
    __stcs((float4*)out + (size_t)p * (DFEAT / 4) + lane, o);
}

extern "C" void kernel_launch(void* const* d_in, const int* in_sizes, int n_in,
                              void* d_out, int out_size)
{
    const float* coords    = (const float*)d_in[0];
    const int*   idx       = (const int*)  d_in[1];
    const int*   smpl_F    = (const int*)  d_in[2];
    const int*   fid       = (const int*)  d_in[3];
    const float* weights   = (const float*)d_in[4];
    const float* sdf       = (const float*)d_in[5];
    const float* hitpt     = (const float*)d_in[6];
    const float* codebooks = (const float*)d_in[7];
    float*       out       = (float*)d_out;

    int BS = in_sizes[3];       // B*S
    int B  = in_sizes[1];       // batch
    int S  = BS / B;
    int nFaces = in_sizes[2] / 3;

    int Sshift = -1;
    if ((S & (S - 1)) == 0) {
        Sshift = 0;
        while ((1 << Sshift) < S) Sshift++;
    }

    // P1: face-vertex int4 table.
    face_table_kernel<<<(nFaces + 255) / 256, 256>>>(smpl_F, nFaces);

    // P2: fp16 codebook copies for active subjects.
    int convThreads = NUM_VERTICES * DFEAT / 4;   // float4 units
    dim3 gridC((convThreads + 255) / 256, B);
    convert_kernel<<<gridC, 256>>>(idx, codebooks);

    // K: fused gather+tail, 16:1 interleave.
    int NB = (BS + 255) / 256;
    long long NA = ((long long)BS * 16 + 255) / 256;
    long long total = NA + NB;

    fused_kernel<<<(unsigned)total, 256>>>(
        coords, fid, weights, sdf, hitpt, out, BS, S, Sshift);
}

// round 15
// speedup vs baseline: 1.1685x; 1.1685x over previous
#include <cuda_runtime.h>
#include <cuda_fp16.h>
#include <cstdint>

// FeatureDictionary — fp16-codebook, 8-lane gather, single merged prepass.
//  P: (one launch) face table int4 expand + f32->fp16 codebook convert
//  K: fused 8:1 block-specialized kernel
//     gather blocks: 8 lanes/point, 3 one-line fp16 gathers, f32 accumulate
//     tail blocks:   normal + coords_feats streaming
//  0 coords [B,S,3] f32   1 idx [B] i32         2 smpl_F [13776,3] i32
//  3 fid [B,S] i32        4 weights [B,S,3] f32  5 sdf [B,S,1] f32
//  6 hitpt [B,S,3] f32    7 codebooks [256,6890,64] f32
// Output: concat( weighted_feats [B,S,64], coords_feats [B,S,3], normal [B,S,3] )

#define NUM_VERTICES 6890
#define NUM_FACES_MAX 16384
#define DFEAT 64
#define MAXB 8
#define CB_U2 (NUM_VERTICES * DFEAT / 4)   // uint2 units per subject = 110240

__device__ int4   g_faceVerts[NUM_FACES_MAX];
__device__ __half g_cbh[MAXB * NUM_VERTICES * DFEAT];   // 7MB fp16 scratch

// Merged prepass: flat index covers B*CB_U2 convert units then nFaces faces.
__global__ __launch_bounds__(256)
void prepass_kernel(const int* __restrict__ idx,
                    const float* __restrict__ codebooks,
                    const int* __restrict__ smpl_F,
                    int B, int nFaces)
{
    int t = blockIdx.x * blockDim.x + threadIdx.x;
    int convTotal = B * CB_U2;

    if (t < convTotal) {
        int b = t / CB_U2;
        int u = t - b * CB_U2;
        int subj = __ldg(idx + b);
        const float4* src = (const float4*)(codebooks
                            + (size_t)subj * (NUM_VERTICES * DFEAT));
        uint2* dst = (uint2*)(g_cbh + (size_t)b * (NUM_VERTICES * DFEAT));
        float4 v = __ldcs(src + u);
        __half2 lo = __floats2half2_rn(v.x, v.y);
        __half2 hi = __floats2half2_rn(v.z, v.w);
        uint2 o;
        o.x = *(unsigned*)&lo;
        o.y = *(unsigned*)&hi;
        dst[u] = o;
    } else {
        int ft = t - convTotal;
        if (ft < nFaces) {
            int v0 = __ldg(smpl_F + 3 * ft + 0);
            int v1 = __ldg(smpl_F + 3 * ft + 1);
            int v2 = __ldg(smpl_F + 3 * ft + 2);
            g_faceVerts[ft] = make_int4(v0, v1, v2, 0);
        }
    }
}

__device__ __forceinline__ void fma8(float* o, float w, uint4 R)
{
    float2 x0 = __half22float2(*(__half2*)&R.x);
    float2 x1 = __half22float2(*(__half2*)&R.y);
    float2 x2 = __half22float2(*(__half2*)&R.z);
    float2 x3 = __half22float2(*(__half2*)&R.w);
    o[0] += w * x0.x;  o[1] += w * x0.y;
    o[2] += w * x1.x;  o[3] += w * x1.y;
    o[4] += w * x2.x;  o[5] += w * x2.y;
    o[6] += w * x3.x;  o[7] += w * x3.y;
}

__global__ __launch_bounds__(256)
void fused_kernel(const float* __restrict__ coords,
                  const int*   __restrict__ fid,
                  const float* __restrict__ weights,
                  const float* __restrict__ sdf,
                  const float* __restrict__ hitpt,
                  float*       __restrict__ out,
                  int BS, int S, int Sshift)
{
    // Block-type decode: every 9th block (r==8) is a tail block.
    int blk = blockIdx.x;
    int q   = blk / 9;
    int r   = blk - q * 9;

    if (r == 8) {
        int p = q * 256 + threadIdx.x;
        if (p >= BS) return;

        size_t C_OFF = (size_t)BS * DFEAT;
        size_t N_OFF = C_OFF + (size_t)BS * 3;

        float cx = __ldcs(coords + 3 * p + 0);
        float cy = __ldcs(coords + 3 * p + 1);
        float cz = __ldcs(coords + 3 * p + 2);
        float hx = __ldcs(hitpt  + 3 * p + 0);
        float hy = __ldcs(hitpt  + 3 * p + 1);
        float hz = __ldcs(hitpt  + 3 * p + 2);
        float w1 = __ldcs(weights + 3 * p + 1);
        float w2 = __ldcs(weights + 3 * p + 2);
        float sd = __ldcs(sdf + p);

        float dx = hx - cx, dy = hy - cy, dz = hz - cz;
        float nrm = sqrtf(dx * dx + dy * dy + dz * dz);
        float inv = 1.0f / fmaxf(nrm, 1e-6f);

        __stcs(out + N_OFF + 3 * (size_t)p + 0, dx * inv);
        __stcs(out + N_OFF + 3 * (size_t)p + 1, dy * inv);
        __stcs(out + N_OFF + 3 * (size_t)p + 2, dz * inv);
        __stcs(out + C_OFF + 3 * (size_t)p + 0, w1);
        __stcs(out + C_OFF + 3 * (size_t)p + 1, w2);
        __stcs(out + C_OFF + 3 * (size_t)p + 2, sd);
        return;
    }

    // ---- gather path: 8 lanes/point, fp16 rows (128B = 1 line each) ----
    int gblk = q * 8 + r;
    int L    = gblk * 256 + threadIdx.x;
    int p    = L >> 3;
    int lane = L & 7;
    if (p >= BS) return;

    int b = (Sshift >= 0) ? (p >> Sshift) : (p / S);
    const __half* cb = g_cbh + (size_t)b * (NUM_VERTICES * DFEAT);

    int f = __ldcs(fid + p);
    int4 v = __ldg(&g_faceVerts[f]);

    float w0 = __ldcs(weights + 3 * p + 0);
    float w1 = __ldcs(weights + 3 * p + 1);
    float w2 = __ldcs(weights + 3 * p + 2);

    // One 16B load per row per lane: 8 lanes cover the 128B row/line.
    const uint4* r0 = (const uint4*)(cb + (size_t)v.x * DFEAT);
    const uint4* r1 = (const uint4*)(cb + (size_t)v.y * DFEAT);
    const uint4* r2 = (const uint4*)(cb + (size_t)v.z * DFEAT);

    uint4 A = __ldg(r0 + lane);
    uint4 C = __ldg(r1 + lane);
    uint4 D = __ldg(r2 + lane);

    float o[8] = {0,0,0,0,0,0,0,0};
    fma8(o, w0, A);
    fma8(o, w1, C);
    fma8(o, w2, D);

    // Lane covers output floats [8*lane, 8*lane+8): two coalesced float4s.
    float4* outv = (float4*)out + (size_t)p * (DFEAT / 4) + 2 * lane;
    __stcs(outv,     make_float4(o[0], o[1], o[2], o[3]));
    __stcs(outv + 1, make_float4(o[4], o[5], o[6], o[7]));
}

extern "C" void kernel_launch(void* const* d_in, const int* in_sizes, int n_in,
                              void* d_out, int out_size)
{
    const float* coords    = (const float*)d_in[0];
    const int*   idx       = (const int*)  d_in[1];
    const int*   smpl_F    = (const int*)  d_in[2];
    const int*   fid       = (const int*)  d_in[3];
    const float* weights   = (const float*)d_in[4];
    const float* sdf       = (const float*)d_in[5];
    const float* hitpt     = (const float*)d_in[6];
    const float* codebooks = (const float*)d_in[7];
    float*       out       = (float*)d_out;

    int BS = in_sizes[3];       // B*S
    int B  = in_sizes[1];       // batch
    int S  = BS / B;
    int nFaces = in_sizes[2] / 3;

    int Sshift = -1;
    if ((S & (S - 1)) == 0) {
        Sshift = 0;
        while ((1 << Sshift) < S) Sshift++;
    }

    // P: merged prepass (convert + face table), single launch.
    long long prework = (long long)B * CB_U2 + nFaces;
    prepass_kernel<<<(unsigned)((prework + 255) / 256), 256>>>(
        idx, codebooks, smpl_F, B, nFaces);

    // K: fused gather+tail, 8:1 interleave.
    int NB = (BS + 255) / 256;
    long long NA = ((long long)BS * 8 + 255) / 256;
    long long total = NA + NB;

    fused_kernel<<<(unsigned)total, 256>>>(
        coords, fid, weights, sdf, hitpt, out, BS, S, Sshift);
}